// round 11
// baseline (speedup 1.0000x reference)
#include <cuda_runtime.h>

// SparseTopKLayer: out = x + ((x*rms)*w)*mask*gamma
//   rms = rsqrt(mean(x^2)+1e-6); mask = |x_norm| >= kth_largest(|x_norm|, k)
// Rank on |x*w| (rms>0 row-constant -> identical ordering).
// One CTA per row, 256 threads, 8 elems/thread in registers.
// Gaussian-quantile open-top window; adaptive histogram select with per-bin
// min/max fused into the INSERT path (cheap: ~1.4 inserts/thread), scan on
// warp0 only, so every exit resolves without a block-wide rescan pass.
// Exact for arbitrary data via re-windowing.

constexpr int D    = 2048;
constexpr int T    = 256;
constexpr int BINS = 128;

// smem: [0,256)=cnt[2][128]  [256,512)=mnv[2][128]  [512,768)=mxv[2][128]
#define CNT(p) (sbuf + (p) * BINS)
#define MNV(p) (sbuf + 256 + (p) * BINS)
#define MXV(p) (sbuf + 512 + (p) * BINS)

__device__ __forceinline__ float inv_phi_tail(float q) {
    // Phi^{-1}(1-q), q in (0,0.5]; Abramowitz-Stegun 26.2.23, |err|<4.5e-4
    q = fminf(fmaxf(q, 1e-7f), 0.4999f);
    float s = sqrtf(-2.0f * __logf(q));
    return s - (2.30753f + 0.27061f * s) / (1.0f + s * (0.99229f + 0.04481f * s));
}

__global__ void __launch_bounds__(T, 6) sparse_topk_kernel(
    const float* __restrict__ x,
    const float* __restrict__ w,
    const float* __restrict__ g,
    const int* __restrict__ kptr,
    float* __restrict__ out)
{
    const int row  = blockIdx.x;
    const int t    = threadIdx.x;
    const int lane = t & 31;
    const int wid  = t >> 5;

    __shared__ float    red[8];
    __shared__ __align__(16) unsigned sbuf[768];
    __shared__ unsigned lo_sh, thr_sh;
    __shared__ int      r_sh, s_sh, mode_sh, hi_open_sh;

    // ---- load x,w once; xw in regs; sum of x^2 ----
    const float4* xr = reinterpret_cast<const float4*>(x) + (size_t)row * (D / 4);
    const float4* wv = reinterpret_cast<const float4*>(w);
    float4 xa = xr[t], xb = xr[t + T];
    float4 wa = wv[t], wb = wv[t + T];

    float xv[8] = {xa.x,xa.y,xa.z,xa.w,xb.x,xb.y,xb.z,xb.w};
    float xw[8];
    float ss = 0.0f;
    {
        float wf[8] = {wa.x,wa.y,wa.z,wa.w,wb.x,wb.y,wb.z,wb.w};
        #pragma unroll
        for (int i = 0; i < 8; i++) {
            xw[i] = xv[i] * wf[i];
            ss = fmaf(xv[i], xv[i], ss);
        }
    }
    #pragma unroll
    for (int o = 16; o > 0; o >>= 1)
        ss += __shfl_xor_sync(0xffffffffu, ss, o);
    if (lane == 0) red[wid] = ss;
    // zero all buffer pairs: cnt=0, mnv=MAX, mxv=0
    sbuf[t]       = 0u;
    sbuf[256 + t] = 0xFFFFFFFFu;
    sbuf[512 + t] = 0u;
    __syncthreads();

    // ---- warp0: rms + quantile window (open top) ----
    __shared__ float rms_sh;
    if (t < 8) {
        float v = red[t];
        #pragma unroll
        for (int o = 4; o > 0; o >>= 1) v += __shfl_xor_sync(0xffu, v, o);
        if (t == 0) {
            float ms = v * (1.0f / (float)D);
            rms_sh = rsqrtf(ms + 1e-6f);
            float sigma = sqrtf(ms);            // |w|~1 heuristic (window only)
            int k = *kptr;
            float t1 = inv_phi_tail((float)(k + 96) * (0.5f / (float)D));
            float t2 = inv_phi_tail((float)(k - 96 > 1 ? k - 96 : 1) * (0.5f / (float)D));
            unsigned lo = (t1 > 0.0f) ? __float_as_uint(t1 * sigma) : 0u;
            unsigned hq = __float_as_uint(fmaxf(t2, 0.0f) * sigma);
            if (hq <= lo) hq = lo + 1u;
            unsigned wsoft = hq - lo;
            lo_sh = lo;
            hi_open_sh = 1;                     // window is [lo, +inf)
            s_sh  = (wsoft > (unsigned)BINS) ? (25 - __clz(wsoft - 1u)) : 0;
            r_sh  = k; mode_sh = 0;
        }
    }
    __syncthreads();

    // ---- adaptive-window histogram select ----
    unsigned thr = 0u;
    int p = 0;
    while (true) {
        const unsigned lo = lo_sh;
        const int s = s_sh;
        const bool open = (hi_open_sh != 0);
        // window width in bins is always BINS (tail clamped when open)
        unsigned* hc = CNT(p);
        unsigned* hn = MNV(p);
        unsigned* hx = MXV(p);
        #pragma unroll
        for (int i = 0; i < 8; i++) {
            unsigned ub = __float_as_uint(xw[i]) & 0x7FFFFFFFu;
            unsigned d = ub - lo;
            if (ub >= lo) {                      // candidate at/above window base
                unsigned b = d >> s;
                if (b > (unsigned)(BINS - 1)) {
                    if (!open) continue;         // above closed window: skip
                    b = BINS - 1;                // open: fold tail into last bin
                }
                atomicAdd(&hc[b], 1u);
                atomicMin(&hn[b], ub);
                atomicMax(&hx[b], ub);
            }
        }
        // prep the other buffer set for a possible next round
        if (t < BINS) {
            CNT(p ^ 1)[t] = 0u;
            MNV(p ^ 1)[t] = 0xFFFFFFFFu;
        } else {
            MXV(p ^ 1)[t - BINS] = 0u;
        }
        __syncthreads();

        if (t < 32) {   // warp0: suffix scan + classify + publish (all exits here)
            uint4 hv = *reinterpret_cast<const uint4*>(&hc[lane * 4]);
            unsigned hr[4] = {hv.x, hv.y, hv.z, hv.w};
            unsigned bsum = hr[0] + hr[1] + hr[2] + hr[3];
            unsigned S = bsum;
            #pragma unroll
            for (int o = 1; o < 32; o <<= 1) {
                unsigned v = __shfl_down_sync(0xffffffffu, S, o);
                if (lane + o < 32) S += v;
            }
            unsigned total = __shfl_sync(0xffffffffu, S, 0);
            int r = r_sh;

            if ((unsigned)r > total) {           // threshold below window
                if (lane == 0) {
                    unsigned nrange = lo;        // new window [0, lo)
                    lo_sh = 0u; hi_open_sh = 0;
                    // closed window [0, lo): width lo, need lo <= BINS<<s
                    s_sh = (nrange > (unsigned)BINS) ? (25 - __clz(nrange - 1u)) : 0;
                    r_sh = r - (int)total; mode_sh = 0;
                }
            } else {
                unsigned suf = S - bsum;         // count in strictly-higher lanes
                int bj = -1; unsigned cb = 0, abv = 0;
                #pragma unroll
                for (int j = 3; j >= 0; j--) {
                    unsigned ns = suf + hr[j];
                    if (suf < (unsigned)r && ns >= (unsigned)r) { bj = j; cb = hr[j]; abv = suf; }
                    suf = ns;
                }
                unsigned bal = __ballot_sync(0xffffffffu, bj >= 0);
                int src = __ffs(bal) - 1;
                unsigned B = __shfl_sync(0xffffffffu, (unsigned)(lane * 4 + bj), src);
                cb  = __shfl_sync(0xffffffffu, cb, src);
                abv = __shfl_sync(0xffffffffu, abv, src);
                if (lane == 0) {
                    int r2 = r - (int)abv;
                    if ((int)cb == r2)      { mode_sh = 1; thr_sh = hn[B]; } // min of bucket
                    else if (r2 == 1)       { mode_sh = 1; thr_sh = hx[B]; } // max of bucket
                    else {
                        // narrow into bucket B; use its true value extent
                        unsigned bmin = hn[B], bmax = hx[B];
                        unsigned nrange = bmax - bmin;       // cb>=2 -> bmax>bmin
                        if (nrange <= 1u) { mode_sh = 1; thr_sh = bmax; /* r2>=? */
                            // two distinct values at most: r2<cb and cb==count in
                            // [bmin,bmax]; if exactly 2 values: r2==1 handled above,
                            // so r2>=2 -> thr = bmin
                            thr_sh = bmin;
                        } else {
                            lo_sh = bmin; hi_open_sh = 0; r_sh = r2; mode_sh = 0;
                            // window [bmin, bmax+1): width nrange+1
                            unsigned wd = nrange + 1u;
                            s_sh = (wd > (unsigned)BINS) ? (25 - __clz(wd - 1u)) : 0;
                        }
                    }
                }
            }
        }
        __syncthreads();

        if (mode_sh == 1) { thr = thr_sh; break; }
        p ^= 1;
    }

    // ---- epilogue: out = x + (xw*rms)*g where |xw| >= thr ----
    const float4* gv = reinterpret_cast<const float4*>(g);
    float4 ga = gv[t], gb = gv[t + T];
    float gf[8] = {ga.x,ga.y,ga.z,ga.w,gb.x,gb.y,gb.z,gb.w};
    const float rms  = rms_sh;
    const float thrf = __uint_as_float(thr);

    float fo[8];
    #pragma unroll
    for (int i = 0; i < 8; i++) {
        float keep = (fabsf(xw[i]) >= thrf) ? (rms * gf[i]) : 0.0f;
        fo[i] = fmaf(xw[i], keep, xv[i]);
    }
    float4* orow = reinterpret_cast<float4*>(out) + (size_t)row * (D / 4);
    orow[t]     = make_float4(fo[0], fo[1], fo[2], fo[3]);
    orow[t + T] = make_float4(fo[4], fo[5], fo[6], fo[7]);
}

extern "C" void kernel_launch(void* const* d_in, const int* in_sizes, int n_in,
                              void* d_out, int out_size)
{
    const float* x = (const float*)d_in[0];
    const float* w = (const float*)d_in[1];
    const float* g = (const float*)d_in[2];
    const int*   k = (const int*)d_in[3];

    int N = in_sizes[0] / D;   // 32768 rows
    sparse_topk_kernel<<<N, T>>>(x, w, g, k, (float*)d_out);
}